// round 9
// baseline (speedup 1.0000x reference)
#include <cuda_runtime.h>
#include <cuda_fp16.h>
#include <cstdint>

// Problem constants
#define B_ 4
#define T_ 2048
#define C_ 2048
#define H_ 16
#define D_ 128

// Scratch (device globals: allocation-free per harness rules)
__device__ __half g_Qh[(size_t)B_ * H_ * T_ * D_];   // [B,H,T,Dh]
__device__ __half g_Kh[(size_t)B_ * H_ * T_ * D_];
__device__ __half g_Vh[(size_t)B_ * H_ * T_ * D_];
__device__ __half g_ATTh[(size_t)B_ * T_ * C_];      // [B,T,C]
__device__ __half g_xh[(size_t)B_ * T_ * C_];        // half x
__device__ __half g_wqkvh[(size_t)3 * C_ * C_];      // half qkv_w
__device__ __half g_wprojh[(size_t)C_ * C_];         // half proj_w

// ---------------------------------------------------------------------------
// Helpers (sm_80-class PTX only — safe on base sm_103 target)
// ---------------------------------------------------------------------------
__device__ __forceinline__ uint32_t smem_u32(const void* p) {
    uint32_t a;
    asm("{ .reg .u64 t; cvta.to.shared.u64 t, %1; cvt.u32.u64 %0, t; }"
        : "=r"(a) : "l"(p));
    return a;
}
__device__ __forceinline__ void cpa16(uint32_t dst, const void* src) {
    asm volatile("cp.async.cg.shared.global [%0], [%1], 16;"
                 :: "r"(dst), "l"(src));
}
#define CP_COMMIT() asm volatile("cp.async.commit_group;" ::: "memory")
#define CP_WAIT(n)  asm volatile("cp.async.wait_group " #n ";" ::: "memory")

#define LDSM_X4(r0, r1, r2, r3, addr) \
    asm volatile("ldmatrix.sync.aligned.m8n8.x4.shared.b16 {%0,%1,%2,%3}, [%4];" \
        : "=r"(r0), "=r"(r1), "=r"(r2), "=r"(r3) : "r"(addr))
#define LDSM_X4T(r0, r1, r2, r3, addr) \
    asm volatile("ldmatrix.sync.aligned.m8n8.x4.trans.shared.b16 {%0,%1,%2,%3}, [%4];" \
        : "=r"(r0), "=r"(r1), "=r"(r2), "=r"(r3) : "r"(addr))

// D(16x8,f32) += A(16x16,f16) * B(16x8,f16)
__device__ __forceinline__ void mma_h(float c[4], const uint32_t a[4],
                                      const uint32_t b[2]) {
    asm volatile(
        "mma.sync.aligned.m16n8k16.row.col.f32.f16.f16.f32 "
        "{%0,%1,%2,%3}, {%4,%5,%6,%7}, {%8,%9}, {%0,%1,%2,%3};"
        : "+f"(c[0]), "+f"(c[1]), "+f"(c[2]), "+f"(c[3])
        : "r"(a[0]), "r"(a[1]), "r"(a[2]), "r"(a[3]), "r"(b[0]), "r"(b[1]));
}

// ---------------------------------------------------------------------------
// Prep: fp32 -> fp16 convert, all three matrices in one launch
// ---------------------------------------------------------------------------
#define NX4  (B_ * T_ * C_ / 4)
#define NQ4  (3 * C_ * C_ / 4)
#define NP4  (C_ * C_ / 4)

__global__ void prep_all(const float4* __restrict__ x,
                         const float4* __restrict__ wqkv,
                         const float4* __restrict__ wproj)
{
    int i = blockIdx.x * blockDim.x + threadIdx.x;
    const float4* src;
    __half* dst;
    int j;
    if (i < NX4)            { src = x;     dst = g_xh;     j = i; }
    else if (i < NX4 + NQ4) { src = wqkv;  dst = g_wqkvh;  j = i - NX4; }
    else if (i < NX4 + NQ4 + NP4) { src = wproj; dst = g_wprojh; j = i - NX4 - NQ4; }
    else return;
    float4 v = src[j];
    __half2 h0 = __floats2half2_rn(v.x, v.y);
    __half2 h1 = __floats2half2_rn(v.z, v.w);
    uint2 u;
    u.x = *(uint32_t*)&h0;
    u.y = *(uint32_t*)&h1;
    ((uint2*)dst)[j] = u;
}

// ===========================================================================
// fp16 GEMM — unchanged from Round-8 passing version (at tensor-pipe floor).
// CTA 128x128, 8 warps (2m x 4n) at 64x32. BK=128, 3-stage cp.async.
// ===========================================================================
#define GRB 272
#define STG_B (256 * GRB)
#define GEMM_SMEM (3 * STG_B)            // 208896

__global__ void __launch_bounds__(256, 1)
gemm_h(const float* __restrict__ bias, float* __restrict__ Out, int mode)
{
    extern __shared__ char smraw[];
    const __half* A = mode ? g_ATTh : g_xh;
    const __half* W = mode ? g_wprojh : g_wqkvh;
    const int K = C_;

    uint32_t sbase = smem_u32(smraw);

    int tid  = threadIdx.x;
    int lane = tid & 31;
    int warp = tid >> 5;
    int g    = lane >> 2;
    int tig  = lane & 3;
    int wm   = warp >> 2;
    int wn   = warp & 3;
    int bm   = blockIdx.y << 7;
    int bn   = blockIdx.x << 7;

    int row0 = tid >> 4;
    int c16  = tid & 15;
    const __half* a_src0 = A + (size_t)(bm + row0) * K + c16 * 8;
    const __half* b_src0 = W + (size_t)(bn + row0) * K + c16 * 8;
    uint32_t stg_a = (uint32_t)(row0 * GRB + c16 * 16);
    uint32_t stg_b = stg_a + 128 * GRB;

    float acc[4][4][4];
#pragma unroll
    for (int i = 0; i < 4; i++)
#pragma unroll
        for (int j = 0; j < 4; j++)
#pragma unroll
            for (int r = 0; r < 4; r++) acc[i][j][r] = 0.f;

    uint32_t a_lane = (uint32_t)((wm * 64 + (lane & 15)) * GRB + ((lane >> 4) << 4));
    uint32_t b_lane = (uint32_t)(128 * GRB +
                      (wn * 32 + ((lane >> 4) << 3) + (lane & 7)) * GRB +
                      (((lane >> 3) & 1) << 4));

#pragma unroll
    for (int st = 0; st < 2; st++) {
        uint32_t ad = sbase + st * STG_B + stg_a;
        uint32_t bd = sbase + st * STG_B + stg_b;
#pragma unroll
        for (int s = 0; s < 8; s++)
            cpa16(ad + s * (16 * GRB), a_src0 + (size_t)st * 128 + (size_t)s * 16 * K);
#pragma unroll
        for (int s = 0; s < 8; s++)
            cpa16(bd + s * (16 * GRB), b_src0 + (size_t)st * 128 + (size_t)s * 16 * K);
        CP_COMMIT();
    }

    uint32_t af[2][4][4], bf[2][4][2];
#define G_LOAD_FRAGS(d, Sb, ks) do {                                            \
    _Pragma("unroll")                                                           \
    for (int ma = 0; ma < 4; ma++)                                              \
        LDSM_X4(af[d][ma][0], af[d][ma][1], af[d][ma][2], af[d][ma][3],         \
                (Sb) + a_lane + ma * (16 * GRB) + (ks) * 32);                   \
    _Pragma("unroll")                                                           \
    for (int np = 0; np < 2; np++)                                              \
        LDSM_X4(bf[d][2 * np][0], bf[d][2 * np][1], bf[d][2 * np + 1][0],       \
                bf[d][2 * np + 1][1],                                           \
                (Sb) + b_lane + np * (16 * GRB) + (ks) * 32);                   \
} while (0)

    const int NKT = 16;
    for (int kt = 0; kt < NKT; kt++) {
        if (kt < NKT - 2) { CP_WAIT(1); } else { CP_WAIT(0); }
        __syncthreads();

        if (kt + 2 < NKT) {
            int st = kt + 2;
            int buf = st - (st / 3) * 3;
            uint32_t ad = sbase + buf * STG_B + stg_a;
            uint32_t bd = sbase + buf * STG_B + stg_b;
#pragma unroll
            for (int s = 0; s < 8; s++)
                cpa16(ad + s * (16 * GRB), a_src0 + (size_t)st * 128 + (size_t)s * 16 * K);
#pragma unroll
            for (int s = 0; s < 8; s++)
                cpa16(bd + s * (16 * GRB), b_src0 + (size_t)st * 128 + (size_t)s * 16 * K);
            CP_COMMIT();
        }

        int buf = kt - (kt / 3) * 3;
        uint32_t Sb = sbase + buf * STG_B;

        G_LOAD_FRAGS(0, Sb, 0);
#pragma unroll
        for (int ks = 0; ks < 8; ks++) {
            int cur = ks & 1;
            if (ks < 7) G_LOAD_FRAGS(cur ^ 1, Sb, ks + 1);
#pragma unroll
            for (int ma = 0; ma < 4; ma++)
#pragma unroll
                for (int na = 0; na < 4; na++)
                    mma_h(acc[ma][na], af[cur][ma], bf[cur][na]);
        }
    }

    int sel = blockIdx.x >> 4;
    int hh  = blockIdx.x & 15;
    __half* qkv_dst = (sel == 0) ? g_Qh : ((sel == 1) ? g_Kh : g_Vh);

#pragma unroll
    for (int ma = 0; ma < 4; ma++) {
        int r0 = bm + (wm << 6) + (ma << 4) + g;
#pragma unroll
        for (int na = 0; na < 4; na++) {
            int cb = (wn << 5) + (na << 3) + (tig << 1);
            int nglob = bn + cb;
            float b0 = __ldg(bias + nglob);
            float b1 = __ldg(bias + nglob + 1);
            if (mode == 0) {
                __half2 v0 = __floats2half2_rn(acc[ma][na][0] + b0,
                                               acc[ma][na][1] + b1);
                __half2 v1 = __floats2half2_rn(acc[ma][na][2] + b0,
                                               acc[ma][na][3] + b1);
                int bb0 = r0 >> 11, t0 = r0 & 2047;
                int r1 = r0 + 8;
                int bb1 = r1 >> 11, t1 = r1 & 2047;
                *(__half2*)(qkv_dst + (((size_t)(bb0 * H_ + hh)) * T_ + t0) * D_ + cb) = v0;
                *(__half2*)(qkv_dst + (((size_t)(bb1 * H_ + hh)) * T_ + t1) * D_ + cb) = v1;
            } else {
                float2 v0 = make_float2(acc[ma][na][0] + b0, acc[ma][na][1] + b1);
                float2 v1 = make_float2(acc[ma][na][2] + b0, acc[ma][na][3] + b1);
                *(float2*)(Out + (size_t)r0 * C_ + nglob)       = v0;
                *(float2*)(Out + (size_t)(r0 + 8) * C_ + nglob) = v1;
            }
        }
    }
}

// ===========================================================================
// Flash attention, FA2-style warp-row ownership (fp16 mma, fp32 softmax).
// CTA: 128 queries, 8 warps; warp w owns q rows [16w,16w+16) x ALL 128 keys.
// Softmax fully warp-local (no cross-warp smem reductions, 2 barriers/kb).
// P feeds PV directly from registers (C-frag == A-frag layout, no P smem).
// Causal diag-block: warp-uniform tile skipping (np<=w in S, kc<=w in PV).
// K/V double-buffered: smem = Q + 2x(K,V) = 5 tiles = 174080 bytes.
// ===========================================================================
#define ARB 272                           // bytes per smem row (128 halfs + pad)
#define TILE_B (128 * ARB)                // 34816
#define ATT_SMEM (5 * TILE_B)             // 174080

__global__ void __launch_bounds__(256, 1)
attn_h()
{
    extern __shared__ char smraw[];
    uint32_t sbase = smem_u32(smraw);
    uint32_t q_sm = sbase;

    int tid  = threadIdx.x;
    int lane = tid & 31;
    int w    = tid >> 5;                  // warp 0..7 -> q rows [16w, 16w+16)
    int g    = lane >> 2;
    int t    = lane & 3;

    int qb = (int)gridDim.x - 1 - (int)blockIdx.x;   // heavy blocks first
    int bh = blockIdx.y;
    size_t bhoff = (size_t)bh * T_ * D_;

    // staging: chunk id c = tid + 256*s -> row=(tid>>4)+16s, c4=tid&15
    int row0 = tid >> 4;
    int cc4  = tid & 15;
    uint32_t dst_off = (uint32_t)(row0 * ARB + cc4 * 16);
    size_t   src_off = (size_t)row0 * D_ + cc4 * 8;

    // Q tile (once)
    {
        const __half* qsrc = g_Qh + bhoff + (size_t)qb * 128 * D_ + src_off;
#pragma unroll
        for (int s = 0; s < 8; s++)
            cpa16(q_sm + dst_off + s * (16 * ARB), qsrc + (size_t)s * 16 * D_);
        CP_COMMIT();
    }
    // K/V kb=0 into buffer 0
    {
        const __half* ksrc = g_Kh + bhoff + src_off;
        const __half* vsrc = g_Vh + bhoff + src_off;
        uint32_t k0 = sbase + TILE_B;
        uint32_t v0 = sbase + 2 * TILE_B;
#pragma unroll
        for (int s = 0; s < 8; s++)
            cpa16(k0 + dst_off + s * (16 * ARB), ksrc + (size_t)s * 16 * D_);
#pragma unroll
        for (int s = 0; s < 8; s++)
            cpa16(v0 + dst_off + s * (16 * ARB), vsrc + (size_t)s * 16 * D_);
        CP_COMMIT();
    }

    // ldmatrix per-lane address components
    // Q (A-frag, 16 rows x 16 d per X4): rows 16w + (lane&15), col-half lane>>4
    uint32_t q_lane = (uint32_t)(((w << 4) + (lane & 15)) * ARB + ((lane >> 4) << 4));
    // K (B-frag, non-trans, 16 keys x 16 d per X4)
    uint32_t k_base = (uint32_t)((((lane >> 4) << 3) + (lane & 7)) * ARB +
                                 (((lane >> 3) & 1) << 4));
    // V (B-frag, trans, 16 keys x 16 d per X4T)
    uint32_t v_base = (uint32_t)(((((lane >> 3) & 1) << 3) + (lane & 7)) * ARB +
                                 ((lane >> 4) << 4));

    float oacc[16][4];
#pragma unroll
    for (int i = 0; i < 16; i++)
#pragma unroll
        for (int r = 0; r < 4; r++) oacc[i][r] = 0.f;
    float m_i[2] = {-1.0e30f, -1.0e30f};
    float l_i[2] = {0.f, 0.f};

    const float scale = 0.088388347648318447f;   // 1/sqrt(128)

    for (int kb = 0; kb <= qb; kb++) {
        int buf = kb & 1;
        uint32_t k_sm = sbase + TILE_B + (uint32_t)buf * (2 * TILE_B);
        uint32_t v_sm = k_sm + TILE_B;
        bool diag = (kb == qb);
        int nplim = diag ? (w + 1) : 8;      // key-16-chunks to compute
        int nlim  = nplim << 1;              // key-8-tiles to compute

        __syncthreads();   // prior iteration done reading buf^1 tiles

        if (kb < qb) {     // prefetch kb+1 into the other buffer
            uint32_t kn = sbase + TILE_B + (uint32_t)(buf ^ 1) * (2 * TILE_B);
            uint32_t vn = kn + TILE_B;
            const __half* ksrc = g_Kh + bhoff + (size_t)(kb + 1) * 128 * D_ + src_off;
            const __half* vsrc = g_Vh + bhoff + (size_t)(kb + 1) * 128 * D_ + src_off;
#pragma unroll
            for (int s = 0; s < 8; s++)
                cpa16(kn + dst_off + s * (16 * ARB), ksrc + (size_t)s * 16 * D_);
#pragma unroll
            for (int s = 0; s < 8; s++)
                cpa16(vn + dst_off + s * (16 * ARB), vsrc + (size_t)s * 16 * D_);
            CP_COMMIT();
            CP_WAIT(1);    // kb's data complete; kb+1 still in flight
        } else {
            CP_WAIT(0);
        }
        __syncthreads();

        // ---- S = Q K^T : warp 16q x 128keys (8 ks of d16) ----
        float sacc[16][4];
#pragma unroll
        for (int i = 0; i < 16; i++)
#pragma unroll
            for (int r = 0; r < 4; r++) sacc[i][r] = 0.f;

#pragma unroll
        for (int ks = 0; ks < 8; ks++) {
            uint32_t qf[4];
            LDSM_X4(qf[0], qf[1], qf[2], qf[3], q_sm + q_lane + ks * 32);
            uint32_t kf[16][2];
#pragma unroll
            for (int np = 0; np < 8; np++)
                if (np < nplim)
                    LDSM_X4(kf[2 * np][0], kf[2 * np][1], kf[2 * np + 1][0],
                            kf[2 * np + 1][1],
                            k_sm + k_base + np * (16 * ARB) + ks * 32);
#pragma unroll
            for (int na = 0; na < 16; na++)
                if (na < nlim)
                    mma_h(sacc[na], qf, kf[na]);
        }

        // ---- warp-local softmax ----
        float rmax[2] = {-1.0e30f, -1.0e30f};
#pragma unroll
        for (int na = 0; na < 16; na++)
            if (na < nlim) {
#pragma unroll
                for (int e = 0; e < 4; e++) {
                    float s = sacc[na][e] * scale;
                    if (diag) {
                        int col_l = (na << 3) + (t << 1) + (e & 1);
                        int row_l = (w << 4) + g + ((e >> 1) << 3);
                        if (col_l > row_l) s = -1.0e30f;
                    }
                    sacc[na][e] = s;
                    rmax[e >> 1] = fmaxf(rmax[e >> 1], s);
                }
            }
#pragma unroll
        for (int r = 0; r < 2; r++) {
            rmax[r] = fmaxf(rmax[r], __shfl_xor_sync(0xffffffffu, rmax[r], 1));
            rmax[r] = fmaxf(rmax[r], __shfl_xor_sync(0xffffffffu, rmax[r], 2));
        }
        float mnew[2], alpha[2], rsum[2];
#pragma unroll
        for (int r = 0; r < 2; r++) {
            mnew[r] = fmaxf(m_i[r], rmax[r]);
            alpha[r] = __expf(m_i[r] - mnew[r]);
            m_i[r] = mnew[r];
            rsum[r] = 0.f;
        }

        // p = exp(s - m) (fp32), pack to half2 regs (A-frag layout for PV)
        uint32_t phalf[16][2];
#pragma unroll
        for (int na = 0; na < 16; na++)
            if (na < nlim) {
                float p0 = __expf(sacc[na][0] - mnew[0]);
                float p1 = __expf(sacc[na][1] - mnew[0]);
                float p2 = __expf(sacc[na][2] - mnew[1]);
                float p3 = __expf(sacc[na][3] - mnew[1]);
                rsum[0] += p0 + p1;
                rsum[1] += p2 + p3;
                __half2 h01 = __floats2half2_rn(p0, p1);
                __half2 h23 = __floats2half2_rn(p2, p3);
                phalf[na][0] = *(uint32_t*)&h01;
                phalf[na][1] = *(uint32_t*)&h23;
            }
#pragma unroll
        for (int r = 0; r < 2; r++) {
            rsum[r] += __shfl_xor_sync(0xffffffffu, rsum[r], 1);
            rsum[r] += __shfl_xor_sync(0xffffffffu, rsum[r], 2);
            l_i[r] = l_i[r] * alpha[r] + rsum[r];
        }
#pragma unroll
        for (int nt = 0; nt < 16; nt++) {
            oacc[nt][0] *= alpha[0];
            oacc[nt][1] *= alpha[0];
            oacc[nt][2] *= alpha[1];
            oacc[nt][3] *= alpha[1];
        }

        // ---- O += P V : warp 16q x 128d over 128 keys (8 kc of key16) ----
#pragma unroll
        for (int kc = 0; kc < 8; kc++)
            if (kc < nplim) {
                uint32_t a[4] = {phalf[2 * kc][0], phalf[2 * kc][1],
                                 phalf[2 * kc + 1][0], phalf[2 * kc + 1][1]};
                uint32_t vf[16][2];
#pragma unroll
                for (int nt = 0; nt < 8; nt++)
                    LDSM_X4T(vf[2 * nt][0], vf[2 * nt][1], vf[2 * nt + 1][0],
                             vf[2 * nt + 1][1],
                             v_sm + v_base + kc * (16 * ARB) + nt * 32);
#pragma unroll
                for (int na = 0; na < 16; na++)
                    mma_h(oacc[na], a, vf[na]);
            }
    }

    // ---- epilogue: normalize, half-round, write g_ATTh [B,T,C] ----
    int b  = bh >> 4;
    int hh = bh & 15;
    float inv0 = 1.f / l_i[0];
    float inv1 = 1.f / l_i[1];
    int tg0 = (qb << 7) + (w << 4) + g;
    size_t base0 = ((size_t)b * T_ + tg0) * C_ + (hh << 7);
    size_t base1 = ((size_t)b * T_ + tg0 + 8) * C_ + (hh << 7);
#pragma unroll
    for (int nt = 0; nt < 16; nt++) {
        int d0 = (nt << 3) + (t << 1);
        __half2 v0 = __floats2half2_rn(oacc[nt][0] * inv0, oacc[nt][1] * inv0);
        __half2 v1 = __floats2half2_rn(oacc[nt][2] * inv1, oacc[nt][3] * inv1);
        *(__half2*)(g_ATTh + base0 + d0) = v0;
        *(__half2*)(g_ATTh + base1 + d0) = v1;
    }
}

// ---------------------------------------------------------------------------
extern "C" void kernel_launch(void* const* d_in, const int* in_sizes, int n_in,
                              void* d_out, int out_size)
{
    const float* x      = (const float*)d_in[0];
    const float* qkv_w  = (const float*)d_in[1];
    const float* qkv_b  = (const float*)d_in[2];
    const float* proj_w = (const float*)d_in[3];
    const float* proj_b = (const float*)d_in[4];
    float* out = (float*)d_out;

    cudaFuncSetAttribute(gemm_h, cudaFuncAttributeMaxDynamicSharedMemorySize,
                         GEMM_SMEM);
    cudaFuncSetAttribute(attn_h, cudaFuncAttributeMaxDynamicSharedMemorySize,
                         ATT_SMEM);

    // 0) fp16 conversion of all GEMM inputs (single launch)
    prep_all<<<(NX4 + NQ4 + NP4 + 255) / 256, 256>>>(
        (const float4*)x, (const float4*)qkv_w, (const float4*)proj_w);

    // 1) QKV projection: [8192,2048] @ [6144,2048]^T + b -> g_Qh/g_Kh/g_Vh
    gemm_h<<<dim3(48, 64), 256, GEMM_SMEM>>>(qkv_b, nullptr, 0);

    // 2) causal flash attention (fp16 mma, warp-row FA2) -> g_ATTh [B,T,C]
    attn_h<<<dim3(T_ / 128, B_ * H_), 256, ATT_SMEM>>>();

    // 3) output projection: g_ATTh @ proj_w^T + proj_b -> out (fp32)
    gemm_h<<<dim3(16, 64), 256, GEMM_SMEM>>>(proj_b, out, 1);
}

// round 10
// speedup vs baseline: 1.0407x; 1.0407x over previous
#include <cuda_runtime.h>
#include <cuda_fp16.h>
#include <cstdint>

// Problem constants
#define B_ 4
#define T_ 2048
#define C_ 2048
#define H_ 16
#define D_ 128

// Scratch (device globals: allocation-free per harness rules)
__device__ __half g_Qh[(size_t)B_ * H_ * T_ * D_];   // [B,H,T,Dh]
__device__ __half g_Kh[(size_t)B_ * H_ * T_ * D_];
__device__ __half g_Vh[(size_t)B_ * H_ * T_ * D_];
__device__ __half g_ATTh[(size_t)B_ * T_ * C_];      // [B,T,C]
__device__ __half g_xh[(size_t)B_ * T_ * C_];        // half x
__device__ __half g_wqkvh[(size_t)3 * C_ * C_];      // half qkv_w
__device__ __half g_wprojh[(size_t)C_ * C_];         // half proj_w

// ---------------------------------------------------------------------------
// Helpers (sm_80-class PTX only — safe on base sm_103 target)
// ---------------------------------------------------------------------------
__device__ __forceinline__ uint32_t smem_u32(const void* p) {
    uint32_t a;
    asm("{ .reg .u64 t; cvta.to.shared.u64 t, %1; cvt.u32.u64 %0, t; }"
        : "=r"(a) : "l"(p));
    return a;
}
__device__ __forceinline__ void cpa16(uint32_t dst, const void* src) {
    asm volatile("cp.async.cg.shared.global [%0], [%1], 16;"
                 :: "r"(dst), "l"(src));
}
#define CP_COMMIT() asm volatile("cp.async.commit_group;" ::: "memory")
#define CP_WAIT(n)  asm volatile("cp.async.wait_group " #n ";" ::: "memory")

#define LDSM_X4(r0, r1, r2, r3, addr) \
    asm volatile("ldmatrix.sync.aligned.m8n8.x4.shared.b16 {%0,%1,%2,%3}, [%4];" \
        : "=r"(r0), "=r"(r1), "=r"(r2), "=r"(r3) : "r"(addr))
#define LDSM_X4T(r0, r1, r2, r3, addr) \
    asm volatile("ldmatrix.sync.aligned.m8n8.x4.trans.shared.b16 {%0,%1,%2,%3}, [%4];" \
        : "=r"(r0), "=r"(r1), "=r"(r2), "=r"(r3) : "r"(addr))

// D(16x8,f32) += A(16x16,f16) * B(16x8,f16)
__device__ __forceinline__ void mma_h(float c[4], const uint32_t a[4],
                                      const uint32_t b[2]) {
    asm volatile(
        "mma.sync.aligned.m16n8k16.row.col.f32.f16.f16.f32 "
        "{%0,%1,%2,%3}, {%4,%5,%6,%7}, {%8,%9}, {%0,%1,%2,%3};"
        : "+f"(c[0]), "+f"(c[1]), "+f"(c[2]), "+f"(c[3])
        : "r"(a[0]), "r"(a[1]), "r"(a[2]), "r"(a[3]), "r"(b[0]), "r"(b[1]));
}

// ---------------------------------------------------------------------------
// Prep: fp32 -> fp16 convert, all three matrices in one launch
// ---------------------------------------------------------------------------
#define NX4  (B_ * T_ * C_ / 4)
#define NQ4  (3 * C_ * C_ / 4)
#define NP4  (C_ * C_ / 4)

__global__ void prep_all(const float4* __restrict__ x,
                         const float4* __restrict__ wqkv,
                         const float4* __restrict__ wproj)
{
    int i = blockIdx.x * blockDim.x + threadIdx.x;
    const float4* src;
    __half* dst;
    int j;
    if (i < NX4)            { src = x;     dst = g_xh;     j = i; }
    else if (i < NX4 + NQ4) { src = wqkv;  dst = g_wqkvh;  j = i - NX4; }
    else if (i < NX4 + NQ4 + NP4) { src = wproj; dst = g_wprojh; j = i - NX4 - NQ4; }
    else return;
    float4 v = src[j];
    __half2 h0 = __floats2half2_rn(v.x, v.y);
    __half2 h1 = __floats2half2_rn(v.z, v.w);
    uint2 u;
    u.x = *(uint32_t*)&h0;
    u.y = *(uint32_t*)&h1;
    ((uint2*)dst)[j] = u;
}

// ===========================================================================
// fp16 GEMM — unchanged from Round-8 passing version (at tensor-pipe floor).
// CTA 128x128, 8 warps (2m x 4n) at 64x32. BK=128, 3-stage cp.async.
// ===========================================================================
#define GRB 272
#define STG_B (256 * GRB)
#define GEMM_SMEM (3 * STG_B)            // 208896

__global__ void __launch_bounds__(256, 1)
gemm_h(const float* __restrict__ bias, float* __restrict__ Out, int mode)
{
    extern __shared__ char smraw[];
    const __half* A = mode ? g_ATTh : g_xh;
    const __half* W = mode ? g_wprojh : g_wqkvh;
    const int K = C_;

    uint32_t sbase = smem_u32(smraw);

    int tid  = threadIdx.x;
    int lane = tid & 31;
    int warp = tid >> 5;
    int g    = lane >> 2;
    int tig  = lane & 3;
    int wm   = warp >> 2;
    int wn   = warp & 3;
    int bm   = blockIdx.y << 7;
    int bn   = blockIdx.x << 7;

    int row0 = tid >> 4;
    int c16  = tid & 15;
    const __half* a_src0 = A + (size_t)(bm + row0) * K + c16 * 8;
    const __half* b_src0 = W + (size_t)(bn + row0) * K + c16 * 8;
    uint32_t stg_a = (uint32_t)(row0 * GRB + c16 * 16);
    uint32_t stg_b = stg_a + 128 * GRB;

    float acc[4][4][4];
#pragma unroll
    for (int i = 0; i < 4; i++)
#pragma unroll
        for (int j = 0; j < 4; j++)
#pragma unroll
            for (int r = 0; r < 4; r++) acc[i][j][r] = 0.f;

    uint32_t a_lane = (uint32_t)((wm * 64 + (lane & 15)) * GRB + ((lane >> 4) << 4));
    uint32_t b_lane = (uint32_t)(128 * GRB +
                      (wn * 32 + ((lane >> 4) << 3) + (lane & 7)) * GRB +
                      (((lane >> 3) & 1) << 4));

#pragma unroll
    for (int st = 0; st < 2; st++) {
        uint32_t ad = sbase + st * STG_B + stg_a;
        uint32_t bd = sbase + st * STG_B + stg_b;
#pragma unroll
        for (int s = 0; s < 8; s++)
            cpa16(ad + s * (16 * GRB), a_src0 + (size_t)st * 128 + (size_t)s * 16 * K);
#pragma unroll
        for (int s = 0; s < 8; s++)
            cpa16(bd + s * (16 * GRB), b_src0 + (size_t)st * 128 + (size_t)s * 16 * K);
        CP_COMMIT();
    }

    uint32_t af[2][4][4], bf[2][4][2];
#define G_LOAD_FRAGS(d, Sb, ks) do {                                            \
    _Pragma("unroll")                                                           \
    for (int ma = 0; ma < 4; ma++)                                              \
        LDSM_X4(af[d][ma][0], af[d][ma][1], af[d][ma][2], af[d][ma][3],         \
                (Sb) + a_lane + ma * (16 * GRB) + (ks) * 32);                   \
    _Pragma("unroll")                                                           \
    for (int np = 0; np < 2; np++)                                              \
        LDSM_X4(bf[d][2 * np][0], bf[d][2 * np][1], bf[d][2 * np + 1][0],       \
                bf[d][2 * np + 1][1],                                           \
                (Sb) + b_lane + np * (16 * GRB) + (ks) * 32);                   \
} while (0)

    const int NKT = 16;
    for (int kt = 0; kt < NKT; kt++) {
        if (kt < NKT - 2) { CP_WAIT(1); } else { CP_WAIT(0); }
        __syncthreads();

        if (kt + 2 < NKT) {
            int st = kt + 2;
            int buf = st - (st / 3) * 3;
            uint32_t ad = sbase + buf * STG_B + stg_a;
            uint32_t bd = sbase + buf * STG_B + stg_b;
#pragma unroll
            for (int s = 0; s < 8; s++)
                cpa16(ad + s * (16 * GRB), a_src0 + (size_t)st * 128 + (size_t)s * 16 * K);
#pragma unroll
            for (int s = 0; s < 8; s++)
                cpa16(bd + s * (16 * GRB), b_src0 + (size_t)st * 128 + (size_t)s * 16 * K);
            CP_COMMIT();
        }

        int buf = kt - (kt / 3) * 3;
        uint32_t Sb = sbase + buf * STG_B;

        G_LOAD_FRAGS(0, Sb, 0);
#pragma unroll
        for (int ks = 0; ks < 8; ks++) {
            int cur = ks & 1;
            if (ks < 7) G_LOAD_FRAGS(cur ^ 1, Sb, ks + 1);
#pragma unroll
            for (int ma = 0; ma < 4; ma++)
#pragma unroll
                for (int na = 0; na < 4; na++)
                    mma_h(acc[ma][na], af[cur][ma], bf[cur][na]);
        }
    }

    int sel = blockIdx.x >> 4;
    int hh  = blockIdx.x & 15;
    __half* qkv_dst = (sel == 0) ? g_Qh : ((sel == 1) ? g_Kh : g_Vh);

#pragma unroll
    for (int ma = 0; ma < 4; ma++) {
        int r0 = bm + (wm << 6) + (ma << 4) + g;
#pragma unroll
        for (int na = 0; na < 4; na++) {
            int cb = (wn << 5) + (na << 3) + (tig << 1);
            int nglob = bn + cb;
            float b0 = __ldg(bias + nglob);
            float b1 = __ldg(bias + nglob + 1);
            if (mode == 0) {
                __half2 v0 = __floats2half2_rn(acc[ma][na][0] + b0,
                                               acc[ma][na][1] + b1);
                __half2 v1 = __floats2half2_rn(acc[ma][na][2] + b0,
                                               acc[ma][na][3] + b1);
                int bb0 = r0 >> 11, t0 = r0 & 2047;
                int r1 = r0 + 8;
                int bb1 = r1 >> 11, t1 = r1 & 2047;
                *(__half2*)(qkv_dst + (((size_t)(bb0 * H_ + hh)) * T_ + t0) * D_ + cb) = v0;
                *(__half2*)(qkv_dst + (((size_t)(bb1 * H_ + hh)) * T_ + t1) * D_ + cb) = v1;
            } else {
                float2 v0 = make_float2(acc[ma][na][0] + b0, acc[ma][na][1] + b1);
                float2 v1 = make_float2(acc[ma][na][2] + b0, acc[ma][na][3] + b1);
                *(float2*)(Out + (size_t)r0 * C_ + nglob)       = v0;
                *(float2*)(Out + (size_t)(r0 + 8) * C_ + nglob) = v1;
            }
        }
    }
}

// ===========================================================================
// Flash attention, stripe layout (R8 structure) with 64-query CTAs so that
// TWO CTAs fit per SM (regs <=128 via launch_bounds, smem 89KB): the second
// CTA's MMAs hide this CTA's softmax/barrier/load gaps.
// CTA: 64 queries, 8 warps. S: warps (2 row-halves x 4 key-stripes) 32q x 32k.
// PV: warps (2 row-halves x 4 d-stripes) 32q x 32d over 128 keys.
// P (half) staged over the K buffer. Warp-uniform exact diag skips.
// ===========================================================================
#define ARB 272                           // bytes per smem row (128 halfs + pad)
#define AQ_B (64 * ARB)                   // 17408
#define AK_B (128 * ARB)                  // 34816
#define AK_OFF AQ_B
#define AV_OFF (AQ_B + AK_B)
#define ARED_OFF (AQ_B + 2 * AK_B)        // 87040
#define ATT_SMEM (ARED_OFF + 2 * 4 * 64 * 4)   // 89088

__global__ void __launch_bounds__(256, 2)
attn_h()
{
    extern __shared__ char smraw[];
    uint32_t sbase = smem_u32(smraw);
    uint32_t q_sm = sbase;
    uint32_t k_sm = sbase + AK_OFF;
    uint32_t v_sm = sbase + AV_OFF;
    float* redm = (float*)(smraw + ARED_OFF);    // [4][64]
    float* reds = redm + 4 * 64;                 // [4][64]

    int tid  = threadIdx.x;
    int lane = tid & 31;
    int warp = tid >> 5;
    int g    = lane >> 2;
    int t    = lane & 3;
    int wm2  = warp >> 2;                 // 0..1 : q rows [32*wm2, +32)
    int wq   = warp & 3;                  // key stripe (S) / d stripe (PV)

    int qb = (int)gridDim.x - 1 - (int)blockIdx.x;   // 0..31, heavy first
    int bh = blockIdx.y;
    size_t bhoff = (size_t)bh * T_ * D_;
    int kmax = qb >> 1;
    int doff = (qb & 1) << 6;             // diag column offset: 0 or 64

    // staging: row0 = tid>>4 (0..15), 16B chunk col = tid&15
    int row0 = tid >> 4;
    int cc4  = tid & 15;
    uint32_t dst_off = (uint32_t)(row0 * ARB + cc4 * 16);
    size_t   src_off = (size_t)row0 * D_ + cc4 * 8;

    // Q tile (64 rows, once)
    {
        const __half* qsrc = g_Qh + bhoff + (size_t)qb * 64 * D_ + src_off;
#pragma unroll
        for (int s = 0; s < 4; s++)
            cpa16(q_sm + dst_off + s * (16 * ARB), qsrc + (size_t)s * 16 * D_);
        CP_COMMIT();
    }

    // ldmatrix per-lane address components
    uint32_t qa_lane = (uint32_t)(((wm2 << 5) + (lane & 15)) * ARB + ((lane >> 4) << 4));
    uint32_t kb_rel  = (uint32_t)(((wq << 5) + ((lane >> 4) << 3) + (lane & 7)) * ARB +
                                  (((lane >> 3) & 1) << 4));
    uint32_t vb_rel  = (uint32_t)(((((lane >> 3) & 1) << 3) + (lane & 7)) * ARB +
                                  (wq << 6) + ((lane >> 4) << 4));

    float oacc[2][4][4];
#pragma unroll
    for (int i = 0; i < 2; i++)
#pragma unroll
        for (int j = 0; j < 4; j++)
#pragma unroll
            for (int r = 0; r < 4; r++) oacc[i][j][r] = 0.f;
    float m_i[4], l_i[4];
#pragma unroll
    for (int r = 0; r < 4; r++) { m_i[r] = -1.0e30f; l_i[r] = 0.f; }

    const float scale = 0.088388347648318447f;   // 1/sqrt(128)

    for (int kb = 0; kb <= kmax; kb++) {
        bool diag = (kb == kmax);
        // even-qb diag: key stripes wq>=2 fully masked; PV key-chunks kc>=4 zero
        bool s_skip = diag && ((wq << 5) > doff + 63);
        int  kclim  = diag ? ((doff + 64) >> 4) : 8;

        __syncthreads();   // prior PV done reading P(=K) and V
        {
            const __half* ksrc = g_Kh + bhoff + (size_t)kb * 128 * D_ + src_off;
            const __half* vsrc = g_Vh + bhoff + (size_t)kb * 128 * D_ + src_off;
#pragma unroll
            for (int s = 0; s < 8; s++)
                cpa16(k_sm + dst_off + s * (16 * ARB), ksrc + (size_t)s * 16 * D_);
#pragma unroll
            for (int s = 0; s < 8; s++)
                cpa16(v_sm + dst_off + s * (16 * ARB), vsrc + (size_t)s * 16 * D_);
            CP_COMMIT();
        }
        CP_WAIT(0);
        __syncthreads();

        // ---- S = Q K^T : warp 32q x 32keys, 8 ks of d16 ----
        float sacc[2][4][4];
#pragma unroll
        for (int i = 0; i < 2; i++)
#pragma unroll
            for (int j = 0; j < 4; j++)
#pragma unroll
                for (int r = 0; r < 4; r++) sacc[i][j][r] = 0.f;

        if (!s_skip) {
#pragma unroll
            for (int ks = 0; ks < 8; ks++) {
                uint32_t qf[2][4], kf[4][2];
#pragma unroll
                for (int ma = 0; ma < 2; ma++)
                    LDSM_X4(qf[ma][0], qf[ma][1], qf[ma][2], qf[ma][3],
                            q_sm + qa_lane + ma * (16 * ARB) + ks * 32);
#pragma unroll
                for (int np = 0; np < 2; np++)
                    LDSM_X4(kf[2 * np][0], kf[2 * np][1], kf[2 * np + 1][0],
                            kf[2 * np + 1][1],
                            k_sm + kb_rel + np * (16 * ARB) + ks * 32);
#pragma unroll
                for (int ma = 0; ma < 2; ma++)
#pragma unroll
                    for (int na = 0; na < 4; na++)
                        mma_h(sacc[ma][na], qf[ma], kf[na]);
            }
        }

        // ---- softmax: scale, mask, stripe row max ----
        float rmax[4];
#pragma unroll
        for (int r = 0; r < 4; r++) rmax[r] = -1.0e30f;
#pragma unroll
        for (int ma = 0; ma < 2; ma++)
#pragma unroll
            for (int h = 0; h < 2; h++) {
                int row_l = (wm2 << 5) + (ma << 4) + g + (h << 3);
                int ri = (ma << 1) + h;
#pragma unroll
                for (int na = 0; na < 4; na++)
#pragma unroll
                    for (int e = 0; e < 2; e++) {
                        int col_l = (wq << 5) + (na << 3) + (t << 1) + e;
                        float s = sacc[ma][na][(h << 1) + e] * scale;
                        if (diag && col_l > doff + row_l) s = -1.0e30f;
                        sacc[ma][na][(h << 1) + e] = s;
                        rmax[ri] = fmaxf(rmax[ri], s);
                    }
            }
#pragma unroll
        for (int r = 0; r < 4; r++) {
            rmax[r] = fmaxf(rmax[r], __shfl_xor_sync(0xffffffffu, rmax[r], 1));
            rmax[r] = fmaxf(rmax[r], __shfl_xor_sync(0xffffffffu, rmax[r], 2));
        }
        if (t == 0) {
#pragma unroll
            for (int ma = 0; ma < 2; ma++)
#pragma unroll
                for (int h = 0; h < 2; h++)
                    redm[(wq << 6) + (wm2 << 5) + (ma << 4) + g + (h << 3)] =
                        rmax[(ma << 1) + h];
        }
        __syncthreads();   // all warps done with S reads of K; redm ready

        float alpha[4], mnew[4], rsum[4];
#pragma unroll
        for (int ma = 0; ma < 2; ma++)
#pragma unroll
            for (int h = 0; h < 2; h++) {
                int row_l = (wm2 << 5) + (ma << 4) + g + (h << 3);
                int ri = (ma << 1) + h;
                float m4 = fmaxf(fmaxf(redm[row_l], redm[64 + row_l]),
                                 fmaxf(redm[128 + row_l], redm[192 + row_l]));
                mnew[ri] = fmaxf(m_i[ri], m4);
                alpha[ri] = __expf(m_i[ri] - mnew[ri]);
                m_i[ri] = mnew[ri];
                rsum[ri] = 0.f;
            }
        // p = exp(s - m) (fp32), store half into P (over K buffer)
        __half* Ph = (__half*)(smraw + AK_OFF);
#pragma unroll
        for (int ma = 0; ma < 2; ma++)
#pragma unroll
            for (int h = 0; h < 2; h++) {
                int ri = (ma << 1) + h;
                int row_l = (wm2 << 5) + (ma << 4) + g + (h << 3);
                __half* prow = Ph + (size_t)row_l * 136 + (wq << 5);
#pragma unroll
                for (int na = 0; na < 4; na++) {
                    float p0 = __expf(sacc[ma][na][(h << 1) + 0] - mnew[ri]);
                    float p1 = __expf(sacc[ma][na][(h << 1) + 1] - mnew[ri]);
                    rsum[ri] += p0 + p1;
                    *(__half2*)(prow + (na << 3) + (t << 1)) =
                        __floats2half2_rn(p0, p1);
                }
            }
#pragma unroll
        for (int r = 0; r < 4; r++) {
            rsum[r] += __shfl_xor_sync(0xffffffffu, rsum[r], 1);
            rsum[r] += __shfl_xor_sync(0xffffffffu, rsum[r], 2);
        }
        if (t == 0) {
#pragma unroll
            for (int ma = 0; ma < 2; ma++)
#pragma unroll
                for (int h = 0; h < 2; h++)
                    reds[(wq << 6) + (wm2 << 5) + (ma << 4) + g + (h << 3)] =
                        rsum[(ma << 1) + h];
        }
        __syncthreads();   // P fully written, sums ready

#pragma unroll
        for (int ma = 0; ma < 2; ma++)
#pragma unroll
            for (int h = 0; h < 2; h++) {
                int row_l = (wm2 << 5) + (ma << 4) + g + (h << 3);
                int ri = (ma << 1) + h;
                float ls = reds[row_l] + reds[64 + row_l] +
                           reds[128 + row_l] + reds[192 + row_l];
                l_i[ri] = l_i[ri] * alpha[ri] + ls;
            }
#pragma unroll
        for (int ma = 0; ma < 2; ma++)
#pragma unroll
            for (int na = 0; na < 4; na++) {
                oacc[ma][na][0] *= alpha[(ma << 1)];
                oacc[ma][na][1] *= alpha[(ma << 1)];
                oacc[ma][na][2] *= alpha[(ma << 1) + 1];
                oacc[ma][na][3] *= alpha[(ma << 1) + 1];
            }

        // ---- O += P V : warp 32q x 32d over kclim*16 keys ----
#pragma unroll
        for (int kc = 0; kc < 8; kc++)
            if (kc < kclim) {
                uint32_t pa[2][4], vf[4][2];
#pragma unroll
                for (int ma = 0; ma < 2; ma++)
                    LDSM_X4(pa[ma][0], pa[ma][1], pa[ma][2], pa[ma][3],
                            k_sm + qa_lane + ma * (16 * ARB) + kc * 32);
#pragma unroll
                for (int nt = 0; nt < 2; nt++)
                    LDSM_X4T(vf[2 * nt][0], vf[2 * nt][1], vf[2 * nt + 1][0],
                             vf[2 * nt + 1][1],
                             v_sm + vb_rel + kc * (16 * ARB) + nt * 32);
#pragma unroll
                for (int ma = 0; ma < 2; ma++)
#pragma unroll
                    for (int na = 0; na < 4; na++)
                        mma_h(oacc[ma][na], pa[ma], vf[na]);
            }
    }

    // ---- epilogue: normalize, half-round, write g_ATTh [B,T,C] ----
    int b  = bh >> 4;
    int hh = bh & 15;
#pragma unroll
    for (int ma = 0; ma < 2; ma++)
#pragma unroll
        for (int h = 0; h < 2; h++) {
            int row_l = (wm2 << 5) + (ma << 4) + g + (h << 3);
            int ri = (ma << 1) + h;
            int tg = (qb << 6) + row_l;
            float inv = 1.f / l_i[ri];
            size_t base = ((size_t)b * T_ + tg) * C_ + (hh << 7);
#pragma unroll
            for (int na = 0; na < 4; na++) {
                int d0 = (wq << 5) + (na << 3) + (t << 1);
                __half2 v = __floats2half2_rn(oacc[ma][na][(h << 1) + 0] * inv,
                                              oacc[ma][na][(h << 1) + 1] * inv);
                *(__half2*)(g_ATTh + base + d0) = v;
            }
        }
}

// ---------------------------------------------------------------------------
extern "C" void kernel_launch(void* const* d_in, const int* in_sizes, int n_in,
                              void* d_out, int out_size)
{
    const float* x      = (const float*)d_in[0];
    const float* qkv_w  = (const float*)d_in[1];
    const float* qkv_b  = (const float*)d_in[2];
    const float* proj_w = (const float*)d_in[3];
    const float* proj_b = (const float*)d_in[4];
    float* out = (float*)d_out;

    cudaFuncSetAttribute(gemm_h, cudaFuncAttributeMaxDynamicSharedMemorySize,
                         GEMM_SMEM);
    cudaFuncSetAttribute(attn_h, cudaFuncAttributeMaxDynamicSharedMemorySize,
                         ATT_SMEM);

    // 0) fp16 conversion of all GEMM inputs (single launch)
    prep_all<<<(NX4 + NQ4 + NP4 + 255) / 256, 256>>>(
        (const float4*)x, (const float4*)qkv_w, (const float4*)proj_w);

    // 1) QKV projection: [8192,2048] @ [6144,2048]^T + b -> g_Qh/g_Kh/g_Vh
    gemm_h<<<dim3(48, 64), 256, GEMM_SMEM>>>(qkv_b, nullptr, 0);

    // 2) causal flash attention (fp16 mma, 64q CTAs, 2 CTA/SM) -> g_ATTh
    attn_h<<<dim3(T_ / 64, B_ * H_), 256, ATT_SMEM>>>();

    // 3) output projection: g_ATTh @ proj_w^T + proj_b -> out (fp32)
    gemm_h<<<dim3(16, 64), 256, GEMM_SMEM>>>(proj_b, out, 1);
}